// round 1
// baseline (speedup 1.0000x reference)
#include <cuda_runtime.h>

// Problem constants: B=32, C=8, H=256, W=256
#define NMAPS   256        // B*C
#define HDIM    256
#define WDIM    256
#define HW      65536      // H*W
#define NTHREADS 512

// Scratch for per-(b,c) euclidean distances. __device__ global (no allocation).
__device__ float g_ed[NMAPS];

__global__ __launch_bounds__(NTHREADS)
void dsnt_map_kernel(const float* __restrict__ inp, const float* __restrict__ tgt) {
    const int bc = blockIdx.x;
    const float4* __restrict__ in4 = (const float4*)(inp + (size_t)bc * HW);
    const float4* __restrict__ tg4 = (const float4*)(tgt + (size_t)bc * HW);

    float s = 0.f, sx = 0.f, sy = 0.f;   // sum exp, sum exp*(col+1), sum exp*(row+1)
    float tmax = -1e30f;
    int   tidx = 0;

    // 16384 float4s per map, strided by block threads (coalesced).
    #pragma unroll 4
    for (int j = threadIdx.x; j < HW / 4; j += NTHREADS) {
        float4 a = in4[j];
        float4 t = tg4[j];
        int e0  = j << 2;                 // flat element index of a.x
        int col = e0 & (WDIM - 1);        // 0..252, step 4 within a float4
        int row = e0 >> 8;

        float ex = __expf(a.x);
        float ey = __expf(a.y);
        float ez = __expf(a.z);
        float ew = __expf(a.w);
        float es = (ex + ey) + (ez + ew);

        s  += es;
        sy += es * (float)(row + 1);
        sx += ex * (float)(col + 1) + ey * (float)(col + 2)
            + ez * (float)(col + 3) + ew * (float)(col + 4);

        // argmax of target, first-index tie-break (strict > keeps lowest index
        // within this thread's monotonically increasing scan order)
        if (t.x > tmax) { tmax = t.x; tidx = e0;     }
        if (t.y > tmax) { tmax = t.y; tidx = e0 + 1; }
        if (t.z > tmax) { tmax = t.z; tidx = e0 + 2; }
        if (t.w > tmax) { tmax = t.w; tidx = e0 + 3; }
    }

    // ---- warp reduction ----
    const unsigned FULL = 0xFFFFFFFFu;
    #pragma unroll
    for (int o = 16; o > 0; o >>= 1) {
        s  += __shfl_down_sync(FULL, s,  o);
        sx += __shfl_down_sync(FULL, sx, o);
        sy += __shfl_down_sync(FULL, sy, o);
        float om = __shfl_down_sync(FULL, tmax, o);
        int   oi = __shfl_down_sync(FULL, tidx, o);
        if (om > tmax || (om == tmax && oi < tidx)) { tmax = om; tidx = oi; }
    }

    // ---- cross-warp reduction via shared ----
    __shared__ float sh_s [NTHREADS / 32];
    __shared__ float sh_sx[NTHREADS / 32];
    __shared__ float sh_sy[NTHREADS / 32];
    __shared__ float sh_m [NTHREADS / 32];
    __shared__ int   sh_i [NTHREADS / 32];

    int lane = threadIdx.x & 31;
    int wid  = threadIdx.x >> 5;
    if (lane == 0) {
        sh_s [wid] = s;
        sh_sx[wid] = sx;
        sh_sy[wid] = sy;
        sh_m [wid] = tmax;
        sh_i [wid] = tidx;
    }
    __syncthreads();

    if (wid == 0) {
        const int nw = NTHREADS / 32;   // 16
        s    = (lane < nw) ? sh_s [lane] : 0.f;
        sx   = (lane < nw) ? sh_sx[lane] : 0.f;
        sy   = (lane < nw) ? sh_sy[lane] : 0.f;
        tmax = (lane < nw) ? sh_m [lane] : -1e30f;
        tidx = (lane < nw) ? sh_i [lane] : 0x7FFFFFFF;
        #pragma unroll
        for (int o = 8; o > 0; o >>= 1) {
            s  += __shfl_down_sync(FULL, s,  o);
            sx += __shfl_down_sync(FULL, sx, o);
            sy += __shfl_down_sync(FULL, sy, o);
            float om = __shfl_down_sync(FULL, tmax, o);
            int   oi = __shfl_down_sync(FULL, tidx, o);
            if (om > tmax || (om == tmax && oi < tidx)) { tmax = om; tidx = oi; }
        }
        if (lane == 0) {
            float inv = 1.0f / (s * 256.0f);
            float px = sx * inv;
            float py = sy * inv;
            float tx = (float)((tidx & 255) + 1) * (1.0f / 256.0f);
            float ty = (float)((tidx >> 8)  + 1) * (1.0f / 256.0f);
            float dx = tx - px, dy = ty - py;
            g_ed[bc] = sqrtf(dx * dx + dy * dy);
        }
    }
}

// Deterministic final reduction: sum 256 distances, divide by B=32.
__global__ void dsnt_final_kernel(float* __restrict__ out) {
    __shared__ float sh[8];
    const unsigned FULL = 0xFFFFFFFFu;
    float v = g_ed[threadIdx.x];
    #pragma unroll
    for (int o = 16; o > 0; o >>= 1) v += __shfl_down_sync(FULL, v, o);
    int lane = threadIdx.x & 31;
    int wid  = threadIdx.x >> 5;
    if (lane == 0) sh[wid] = v;
    __syncthreads();
    if (wid == 0) {
        v = (lane < 8) ? sh[lane] : 0.f;
        #pragma unroll
        for (int o = 4; o > 0; o >>= 1) v += __shfl_down_sync(FULL, v, o);
        if (lane == 0) out[0] = v * (1.0f / 32.0f);
    }
}

extern "C" void kernel_launch(void* const* d_in, const int* in_sizes, int n_in,
                              void* d_out, int out_size) {
    const float* inp = (const float*)d_in[0];
    const float* tgt = (const float*)d_in[1];
    float* out = (float*)d_out;
    dsnt_map_kernel<<<NMAPS, NTHREADS>>>(inp, tgt);
    dsnt_final_kernel<<<1, 256>>>(out);
}

// round 2
// speedup vs baseline: 1.0222x; 1.0222x over previous
#include <cuda_runtime.h>

// Problem constants: B=32, C=8, H=256, W=256
#define NMAPS    256        // B*C
#define NBLOCKS  512        // 2 half-map blocks per map
#define NTHREADS 256
#define HW       65536
#define HALF_F4  8192       // float4s per half-map (32768 elems)

// Per-block partials (no allocation: __device__ globals).
__device__ float        g_s [NBLOCKS];
__device__ float        g_sx[NBLOCKS];
__device__ float        g_sy[NBLOCKS];
__device__ float        g_m [NBLOCKS];
__device__ int          g_i [NBLOCKS];
__device__ unsigned int g_count = 0;

__global__ __launch_bounds__(NTHREADS)
void dsnt_fused_kernel(const float* __restrict__ inp,
                       const float* __restrict__ tgt,
                       float* __restrict__ out) {
    const int blk = blockIdx.x;
    // This block covers global float4 range [blk*HALF_F4, (blk+1)*HALF_F4)
    const float4* __restrict__ in4 = (const float4*)inp + (size_t)blk * HALF_F4;
    const float4* __restrict__ tg4 = (const float4*)tgt + (size_t)blk * HALF_F4;
    const int half = blk & 1;              // which half of the map
    const int ebase = half << 15;          // element offset within map (0 or 32768)

    float s = 0.f, sx = 0.f, sy = 0.f;
    float tmax = -1e30f;
    int   tidx = 0;

    // 8192 float4s / 256 threads = 32 iterations, coalesced stride.
    #pragma unroll 8
    for (int j = threadIdx.x; j < HALF_F4; j += NTHREADS) {
        float4 a = in4[j];
        float4 t = tg4[j];
        int e0  = ebase + (j << 2);        // flat element index within the map
        int col = e0 & 255;                // column of a.x
        int row = e0 >> 8;

        float ex = __expf(a.x);
        float ey = __expf(a.y);
        float ez = __expf(a.z);
        float ew = __expf(a.w);
        float es = (ex + ey) + (ez + ew);

        s  += es;
        sy  = fmaf(es, (float)(row + 1), sy);
        // ex*(c+1)+ey*(c+2)+ez*(c+3)+ew*(c+4) = es*(c+1) + ey + 2ez + 3ew
        float extra = fmaf(2.f, ez, ey);
        extra = fmaf(3.f, ew, extra);
        sx += fmaf(es, (float)(col + 1), extra);

        // argmax of target, first-index tie-break (strict >, ascending scan)
        if (t.x > tmax) { tmax = t.x; tidx = e0;     }
        if (t.y > tmax) { tmax = t.y; tidx = e0 + 1; }
        if (t.z > tmax) { tmax = t.z; tidx = e0 + 2; }
        if (t.w > tmax) { tmax = t.w; tidx = e0 + 3; }
    }

    // ---- warp reduction ----
    const unsigned FULL = 0xFFFFFFFFu;
    #pragma unroll
    for (int o = 16; o > 0; o >>= 1) {
        s  += __shfl_down_sync(FULL, s,  o);
        sx += __shfl_down_sync(FULL, sx, o);
        sy += __shfl_down_sync(FULL, sy, o);
        float om = __shfl_down_sync(FULL, tmax, o);
        int   oi = __shfl_down_sync(FULL, tidx, o);
        if (om > tmax || (om == tmax && oi < tidx)) { tmax = om; tidx = oi; }
    }

    // ---- cross-warp reduction (8 warps) ----
    __shared__ float sh_s [8];
    __shared__ float sh_sx[8];
    __shared__ float sh_sy[8];
    __shared__ float sh_m [8];
    __shared__ int   sh_i [8];
    __shared__ bool  isLast;

    const int lane = threadIdx.x & 31;
    const int wid  = threadIdx.x >> 5;
    if (lane == 0) {
        sh_s [wid] = s;  sh_sx[wid] = sx;  sh_sy[wid] = sy;
        sh_m [wid] = tmax;  sh_i [wid] = tidx;
    }
    __syncthreads();

    if (wid == 0) {
        s    = (lane < 8) ? sh_s [lane] : 0.f;
        sx   = (lane < 8) ? sh_sx[lane] : 0.f;
        sy   = (lane < 8) ? sh_sy[lane] : 0.f;
        tmax = (lane < 8) ? sh_m [lane] : -1e30f;
        tidx = (lane < 8) ? sh_i [lane] : 0x7FFFFFFF;
        #pragma unroll
        for (int o = 4; o > 0; o >>= 1) {
            s  += __shfl_down_sync(FULL, s,  o);
            sx += __shfl_down_sync(FULL, sx, o);
            sy += __shfl_down_sync(FULL, sy, o);
            float om = __shfl_down_sync(FULL, tmax, o);
            int   oi = __shfl_down_sync(FULL, tidx, o);
            if (om > tmax || (om == tmax && oi < tidx)) { tmax = om; tidx = oi; }
        }
        if (lane == 0) {
            g_s [blk] = s;  g_sx[blk] = sx;  g_sy[blk] = sy;
            g_m [blk] = tmax;  g_i [blk] = tidx;
            __threadfence();
            unsigned int prev = atomicAdd(&g_count, 1u);
            isLast = (prev == NBLOCKS - 1);
        }
    }
    __syncthreads();

    // ---- last block: combine 512 partials -> 256 distances -> scalar ----
    if (isLast) {
        const int t = threadIdx.x;           // map index 0..255
        float s0  = g_s [2*t],   s1  = g_s [2*t+1];
        float sx0 = g_sx[2*t],   sx1 = g_sx[2*t+1];
        float sy0 = g_sy[2*t],   sy1 = g_sy[2*t+1];
        float m0  = g_m [2*t],   m1  = g_m [2*t+1];
        int   i0  = g_i [2*t],   i1  = g_i [2*t+1];

        float S  = s0 + s1;
        float SX = sx0 + sx1;
        float SY = sy0 + sy1;
        // first half has lower indices: take second half only on strictly greater
        int   I  = (m1 > m0) ? i1 : i0;

        float inv = 1.0f / (S * 256.0f);
        float px = SX * inv;
        float py = SY * inv;
        float tx = (float)((I & 255) + 1) * (1.0f / 256.0f);
        float ty = (float)((I >> 8)  + 1) * (1.0f / 256.0f);
        float dx = tx - px, dy = ty - py;
        float ed = sqrtf(dx * dx + dy * dy);

        // block-sum the 256 distances
        #pragma unroll
        for (int o = 16; o > 0; o >>= 1) ed += __shfl_down_sync(FULL, ed, o);
        __shared__ float sh_ed[8];
        if (lane == 0) sh_ed[wid] = ed;
        __syncthreads();
        if (wid == 0) {
            ed = (lane < 8) ? sh_ed[lane] : 0.f;
            #pragma unroll
            for (int o = 4; o > 0; o >>= 1) ed += __shfl_down_sync(FULL, ed, o);
            if (lane == 0) {
                out[0] = ed * (1.0f / 32.0f);
                g_count = 0;                 // reset for next graph replay
            }
        }
    }
}

extern "C" void kernel_launch(void* const* d_in, const int* in_sizes, int n_in,
                              void* d_out, int out_size) {
    const float* inp = (const float*)d_in[0];
    const float* tgt = (const float*)d_in[1];
    dsnt_fused_kernel<<<NBLOCKS, NTHREADS>>>(inp, tgt, (float*)d_out);
}